// round 1
// baseline (speedup 1.0000x reference)
#include <cuda_runtime.h>

// NeuralODEClassifier: B=65536 elements, 63 Euler steps of tanh-MLP(2->64->2),
// then classifier 2->64->64->3. One thread per element; weights in shared.
//
// tanh(z) = 1 - 2/(exp(2z)+1) = 1 - 2/(2^(C*z)+1), C = 2*log2(e).
// Fold: sum_j W2[j][i]*t_j = (sum_j W2[j][i]) + sum_j (-2*W2[j][i]) * r_j,
// r_j = 1/(2^(w_j)+1), w_j computed directly with C-prescaled W1/b1.

#define H 64
#define TT 64
#define NCLS 3
#define BLOCK 256

__device__ __forceinline__ float fast_ex2(float x) {
    float r; asm("ex2.approx.f32 %0, %1;" : "=f"(r) : "f"(x)); return r;
}
__device__ __forceinline__ float fast_rcp(float x) {
    float r; asm("rcp.approx.f32 %0, %1;" : "=f"(r) : "f"(x)); return r;
}

__global__ __launch_bounds__(BLOCK)
void node_classifier_kernel(
    const float* __restrict__ y0g,  const float* __restrict__ tg,
    const float* __restrict__ W1,   const float* __restrict__ b1,
    const float* __restrict__ W2,   const float* __restrict__ b2,
    const float* __restrict__ Wc1,  const float* __restrict__ bc1,
    const float* __restrict__ Wc2,  const float* __restrict__ bc2,
    const float* __restrict__ Wc3,  const float* __restrict__ bc3,
    float* __restrict__ out, int B)
{
    // --- shared weight cache (packed/prescaled) ---
    __shared__ __align__(16) float sW1z[2][H];   // W1 * 2log2(e)
    __shared__ __align__(16) float sb1z[H];      // b1 * 2log2(e)
    __shared__ __align__(16) float4 sW2n[H / 2]; // -2*W2, pair rows {j:(c0,c1), j+1:(c0,c1)}
    __shared__ float sS[2];                      // sum_j W2[j][i] + b2[i]
    __shared__ float sdt[TT - 1];
    __shared__ __align__(16) float sWc1[2][H];
    __shared__ __align__(16) float sbc1[H];
    __shared__ __align__(16) float sWc2T[H][H];  // transposed: [out_j][in_k]
    __shared__ __align__(16) float sbc2[H];
    __shared__ __align__(16) float4 sWc3[H];     // padded rows {w0,w1,w2,0}
    __shared__ float sbc3[NCLS];

    const float C = 2.88539008177792681472f;     // 2*log2(e)
    const int tid = threadIdx.x;

    if (tid < H) {
        sW1z[0][tid] = W1[tid] * C;
        sW1z[1][tid] = W1[H + tid] * C;
        sb1z[tid]    = b1[tid] * C;
        sWc1[0][tid] = Wc1[tid];
        sWc1[1][tid] = Wc1[H + tid];
        sbc1[tid]    = bc1[tid];
        sbc2[tid]    = bc2[tid];
        sWc3[tid]    = make_float4(Wc3[tid * 3 + 0], Wc3[tid * 3 + 1],
                                   Wc3[tid * 3 + 2], 0.0f);
    }
    if (tid < H / 2) {
        int j4 = tid * 4;  // W2 row-major (64,2): rows tid*2 and tid*2+1
        sW2n[tid] = make_float4(-2.0f * W2[j4 + 0], -2.0f * W2[j4 + 1],
                                -2.0f * W2[j4 + 2], -2.0f * W2[j4 + 3]);
    }
    if (tid < 2) {
        float s = b2[tid];
        #pragma unroll 8
        for (int j = 0; j < H; j++) s += W2[j * 2 + tid];
        sS[tid] = s;
    }
    if (tid < TT - 1) sdt[tid] = tg[tid + 1] - tg[tid];
    if (tid < NCLS)   sbc3[tid] = bc3[tid];
    for (int i = tid; i < H * H; i += BLOCK) {
        int k = i >> 6, j = i & 63;
        sWc2T[j][k] = Wc2[i];
    }
    __syncthreads();

    const int idx = blockIdx.x * BLOCK + tid;
    if (idx >= B) return;

    float ya = y0g[idx * 2 + 0];
    float yb = y0g[idx * 2 + 1];
    const float S0 = sS[0], S1 = sS[1];

    // --- Euler integration: 63 steps ---
    for (int s = 0; s < TT - 1; s++) {
        const float dt = sdt[s];
        float acc0 = 0.0f, acc1 = 0.0f;
        #pragma unroll
        for (int j = 0; j < H; j += 4) {
            const float4 wa = *(const float4*)&sW1z[0][j];
            const float4 wb = *(const float4*)&sW1z[1][j];
            const float4 bb = *(const float4*)&sb1z[j];
            const float4 v0 = sW2n[j / 2];
            const float4 v1 = sW2n[j / 2 + 1];

            float w0 = fmaf(ya, wa.x, fmaf(yb, wb.x, bb.x));
            float w1 = fmaf(ya, wa.y, fmaf(yb, wb.y, bb.y));
            float w2 = fmaf(ya, wa.z, fmaf(yb, wb.z, bb.z));
            float w3 = fmaf(ya, wa.w, fmaf(yb, wb.w, bb.w));

            float r0 = fast_rcp(fast_ex2(w0) + 1.0f);
            float r1 = fast_rcp(fast_ex2(w1) + 1.0f);
            float r2 = fast_rcp(fast_ex2(w2) + 1.0f);
            float r3 = fast_rcp(fast_ex2(w3) + 1.0f);

            acc0 = fmaf(r0, v0.x, acc0); acc1 = fmaf(r0, v0.y, acc1);
            acc0 = fmaf(r1, v0.z, acc0); acc1 = fmaf(r1, v0.w, acc1);
            acc0 = fmaf(r2, v1.x, acc0); acc1 = fmaf(r2, v1.y, acc1);
            acc0 = fmaf(r3, v1.z, acc0); acc1 = fmaf(r3, v1.w, acc1);
        }
        ya = fmaf(dt, S0 + acc0, ya);
        yb = fmaf(dt, S1 + acc1, yb);
    }

    // --- classifier ---
    float h1[H];
    #pragma unroll
    for (int j = 0; j < H; j++) {
        h1[j] = fmaxf(fmaf(ya, sWc1[0][j], fmaf(yb, sWc1[1][j], sbc1[j])), 0.0f);
    }

    float o0 = sbc3[0], o1 = sbc3[1], o2 = sbc3[2];
    for (int j = 0; j < H; j++) {   // rolled over output units
        float s = sbc2[j];
        #pragma unroll
        for (int k = 0; k < H; k += 4) {
            const float4 w = *(const float4*)&sWc2T[j][k];
            s = fmaf(h1[k + 0], w.x, s);
            s = fmaf(h1[k + 1], w.y, s);
            s = fmaf(h1[k + 2], w.z, s);
            s = fmaf(h1[k + 3], w.w, s);
        }
        s = fmaxf(s, 0.0f);
        const float4 wc = sWc3[j];
        o0 = fmaf(s, wc.x, o0);
        o1 = fmaf(s, wc.y, o1);
        o2 = fmaf(s, wc.z, o2);
    }

    out[idx * 3 + 0] = o0;
    out[idx * 3 + 1] = o1;
    out[idx * 3 + 2] = o2;
}

extern "C" void kernel_launch(void* const* d_in, const int* in_sizes, int n_in,
                              void* d_out, int out_size) {
    const float* y0  = (const float*)d_in[0];
    const float* t   = (const float*)d_in[1];
    const float* W1  = (const float*)d_in[2];
    const float* b1  = (const float*)d_in[3];
    const float* W2  = (const float*)d_in[4];
    const float* b2  = (const float*)d_in[5];
    const float* Wc1 = (const float*)d_in[6];
    const float* bc1 = (const float*)d_in[7];
    const float* Wc2 = (const float*)d_in[8];
    const float* bc2 = (const float*)d_in[9];
    const float* Wc3 = (const float*)d_in[10];
    const float* bc3 = (const float*)d_in[11];
    float* out = (float*)d_out;

    const int B = in_sizes[0] / 2;
    const int grid = (B + BLOCK - 1) / BLOCK;
    node_classifier_kernel<<<grid, BLOCK>>>(y0, t, W1, b1, W2, b2,
                                            Wc1, bc1, Wc2, bc2, Wc3, bc3,
                                            out, B);
}